// round 1
// baseline (speedup 1.0000x reference)
#include <cuda_runtime.h>
#include <math.h>

#define NSEG 440
#define NCH  2112
#define HW   65536
#define NH   1024
#define ND   32

// ---------------- scratch (device globals; no allocation allowed) -------------
__device__ float g_sums[NSEG * NCH];
__device__ int   g_cnt[NSEG];
__device__ int   g_hist[NSEG * 3];
__device__ float g_feat[NSEG * NCH];
__device__ float g_fn[NSEG * NCH];
__device__ float g_h1[NSEG * NH];
__device__ float g_h2[NSEG * NH];
__device__ int   g_lab[NSEG];
__device__ float g_aff[NSEG * NSEG];

// ---------------- zero scratch (must run every launch: graph replays) ---------
__global__ void k_zero() {
    int i = blockIdx.x * blockDim.x + threadIdx.x;
    if (i < NSEG * NCH) g_sums[i] = 0.f;
    if (i < NSEG)       g_cnt[i]  = 0;
    if (i < NSEG * 3)   g_hist[i] = 0;
}

// ---------------- per-segment pixel counts + class histogram ------------------
__global__ void k_hist(const int* __restrict__ sp, const int* __restrict__ y) {
    int p = blockIdx.x * blockDim.x + threadIdx.x;
    if (p < HW) {
        int s = sp[p];
        atomicAdd(&g_cnt[s], 1);
        atomicAdd(&g_hist[s * 3 + y[p]], 1);
    }
}

// ---------------- segment feature sums -----------------------------------------
// grid = (NCH/8, 4). Each block: 8 channels, 16384 pixels.
// Coalesced fm loads; privatized smem accumulators (8*440 floats); one global
// atomicAdd per (seg, chan) per block at the end.
__global__ __launch_bounds__(256) void k_seg(const float* __restrict__ fm,
                                             const int* __restrict__ sp) {
    __shared__ float ss[8 * NSEG];
    int tid = threadIdx.x;
    for (int i = tid; i < 8 * NSEG; i += 256) ss[i] = 0.f;
    __syncthreads();

    int c0   = blockIdx.x * 8;
    int base = blockIdx.y * 16384;
    const float* f0 = fm + (size_t)c0 * HW;

    for (int it = 0; it < 64; ++it) {
        int p = base + it * 256 + tid;
        int s = __ldg(&sp[p]);
#pragma unroll
        for (int j = 0; j < 8; ++j) {
            atomicAdd(&ss[j * NSEG + s], __ldg(&f0[(size_t)j * HW + p]));
        }
    }
    __syncthreads();

    for (int i = tid; i < 8 * NSEG; i += 256) {
        int j = i / NSEG;
        int s = i - j * NSEG;
        atomicAdd(&g_sums[(size_t)s * NCH + c0 + j], ss[i]);
    }
}

// ---------------- labels from histogram (exact int replication of reference) --
__global__ void k_lab() {
    int s = blockIdx.x * blockDim.x + threadIdx.x;
    if (s < NSEG) {
        int h0 = g_hist[s * 3 + 0];
        int h1 = g_hist[s * 3 + 1];
        int h2 = g_hist[s * 3 + 2];
        int l = 0, best = h0;
        if (h1 > best) { best = h1; l = 1; }   // argmax, first index on ties
        if (h2 > best) { best = h2; l = 2; }
        if (l == 0) l = (h2 > h1) ? 2 : ((h1 > h2) ? 1 : 0);
        g_lab[s] = l;
    }
}

// ---------------- feat = sums/max(cnt,1); fn = feat/||feat|| -------------------
__global__ __launch_bounds__(256) void k_feat() {
    int s = blockIdx.x;
    int t = threadIdx.x;
    float cnt = (float)g_cnt[s];
    if (cnt < 1.f) cnt = 1.f;
    float sq = 0.f;
    for (int c = t; c < NCH; c += 256) {
        float v = g_sums[(size_t)s * NCH + c] / cnt;
        g_feat[(size_t)s * NCH + c] = v;
        sq += v * v;
    }
    __shared__ float red[256];
    red[t] = sq;
    __syncthreads();
    for (int o = 128; o; o >>= 1) {
        if (t < o) red[t] += red[t + o];
        __syncthreads();
    }
    float nrm = sqrtf(red[0]);
    for (int c = t; c < NCH; c += 256) {
        g_fn[(size_t)s * NCH + c] = g_feat[(size_t)s * NCH + c] / nrm;
    }
}

// ---------------- fp32 GEMM: C = relu(A @ B + bias), A:MxK, B:KxN row-major ----
// block 16x16 threads, 64x64 output tile, 4x4 per thread, BK=16.
__global__ __launch_bounds__(256) void k_gemm_relu(
    const float* __restrict__ A, const float* __restrict__ B,
    const float* __restrict__ bias, float* __restrict__ Cout,
    int M, int N, int K)
{
    __shared__ float As[16][64];
    __shared__ float Bs[16][64];
    int tx = threadIdx.x, ty = threadIdx.y;
    int tid = ty * 16 + tx;
    int row0 = blockIdx.y * 64;
    int col0 = blockIdx.x * 64;

    float acc[4][4] = {};

    int aRow = tid >> 2;          // 0..63
    int aCol = (tid & 3) * 4;     // 0,4,8,12
    int bRow = tid >> 4;          // 0..15
    int bCol = (tid & 15) * 4;    // 0..60

    for (int k0 = 0; k0 < K; k0 += 16) {
        float4 av;
        int gm = row0 + aRow;
        if (gm < M) av = *(const float4*)&A[(size_t)gm * K + k0 + aCol];
        else        av = make_float4(0.f, 0.f, 0.f, 0.f);
        As[aCol + 0][aRow] = av.x;
        As[aCol + 1][aRow] = av.y;
        As[aCol + 2][aRow] = av.z;
        As[aCol + 3][aRow] = av.w;

        float4 bv = *(const float4*)&B[(size_t)(k0 + bRow) * N + col0 + bCol];
        *(float4*)&Bs[bRow][bCol] = bv;
        __syncthreads();

#pragma unroll
        for (int kk = 0; kk < 16; ++kk) {
            float4 a = *(float4*)&As[kk][ty * 4];
            float4 b = *(float4*)&Bs[kk][tx * 4];
            float aa[4] = {a.x, a.y, a.z, a.w};
            float bb[4] = {b.x, b.y, b.z, b.w};
#pragma unroll
            for (int i = 0; i < 4; ++i)
#pragma unroll
                for (int j = 0; j < 4; ++j)
                    acc[i][j] += aa[i] * bb[j];
        }
        __syncthreads();
    }

#pragma unroll
    for (int i = 0; i < 4; ++i) {
        int m = row0 + ty * 4 + i;
        if (m < M) {
#pragma unroll
            for (int j = 0; j < 4; ++j) {
                int n = col0 + tx * 4 + j;
                float v = acc[i][j] + bias[n];
                Cout[(size_t)m * N + n] = fmaxf(v, 0.f);
            }
        }
    }
}

// ---------------- affinity: aff[i][j] = expf(-dot(fn_i, fn_j)) -----------------
__global__ __launch_bounds__(256) void k_aff() {
    __shared__ float As[16][64];
    __shared__ float Bs[16][64];
    int tx = threadIdx.x, ty = threadIdx.y;
    int tid = ty * 16 + tx;
    int i0 = blockIdx.y * 64;
    int j0 = blockIdx.x * 64;

    float acc[4][4] = {};

    int aRow = tid >> 2;
    int aCol = (tid & 3) * 4;

    for (int k0 = 0; k0 < NCH; k0 += 16) {
        int gi = i0 + aRow;
        int gj = j0 + aRow;
        float4 av = (gi < NSEG) ? *(const float4*)&g_fn[(size_t)gi * NCH + k0 + aCol]
                                : make_float4(0.f, 0.f, 0.f, 0.f);
        float4 bv = (gj < NSEG) ? *(const float4*)&g_fn[(size_t)gj * NCH + k0 + aCol]
                                : make_float4(0.f, 0.f, 0.f, 0.f);
        As[aCol + 0][aRow] = av.x; As[aCol + 1][aRow] = av.y;
        As[aCol + 2][aRow] = av.z; As[aCol + 3][aRow] = av.w;
        Bs[aCol + 0][aRow] = bv.x; Bs[aCol + 1][aRow] = bv.y;
        Bs[aCol + 2][aRow] = bv.z; Bs[aCol + 3][aRow] = bv.w;
        __syncthreads();

#pragma unroll
        for (int kk = 0; kk < 16; ++kk) {
            float4 a = *(float4*)&As[kk][ty * 4];
            float4 b = *(float4*)&Bs[kk][tx * 4];
            float aa[4] = {a.x, a.y, a.z, a.w};
            float bb[4] = {b.x, b.y, b.z, b.w};
#pragma unroll
            for (int i = 0; i < 4; ++i)
#pragma unroll
                for (int j = 0; j < 4; ++j)
                    acc[i][j] += aa[i] * bb[j];
        }
        __syncthreads();
    }

#pragma unroll
    for (int i = 0; i < 4; ++i) {
        int gi = i0 + ty * 4 + i;
        if (gi < NSEG) {
#pragma unroll
            for (int j = 0; j < 4; ++j) {
                int gj = j0 + tx * 4 + j;
                if (gj < NSEG)
                    g_aff[gi * NSEG + gj] = expf(-acc[i][j]);
            }
        }
    }
}

// ---------------- MLP tail: h3 = relu(h2@W3+b3); pred = softmax(h3@Wc+bc) -----
__global__ __launch_bounds__(256) void k_head(const float* __restrict__ W3,
                                              const float* __restrict__ b3,
                                              const float* __restrict__ Wc,
                                              const float* __restrict__ bc,
                                              float* __restrict__ out) {
    int r = blockIdx.x;
    int t = threadIdx.x;
    int n = t & 31;
    int ks = t >> 5;   // 8 k-slices of 128
    const float* h2r = g_h2 + (size_t)r * NH;

    float acc = 0.f;
    for (int kk = 0; kk < 128; ++kk) {
        int k = ks * 128 + kk;
        acc += h2r[k] * W3[k * 32 + n];
    }
    __shared__ float red[256];
    __shared__ float h3[32];
    red[t] = acc;
    __syncthreads();
    if (t < 32) {
        float v = red[t];
#pragma unroll
        for (int q = 1; q < 8; ++q) v += red[q * 32 + t];
        v += b3[t];
        h3[t] = fmaxf(v, 0.f);
    }
    __syncthreads();
    if (t == 0) {
        float l0 = bc[0], l1 = bc[1];
#pragma unroll
        for (int d = 0; d < 32; ++d) {
            l0 += h3[d] * Wc[d * 2 + 0];
            l1 += h3[d] * Wc[d * 2 + 1];
        }
        float m = fmaxf(l0, l1);
        float e0 = expf(l0 - m), e1 = expf(l1 - m);
        float inv = 1.f / (e0 + e1);
        out[r * 2 + 0] = e0 * inv;
        out[r * 2 + 1] = e1 * inv;
    }
}

// ---------------- label propagation: masked argmax over aff row ---------------
__global__ __launch_bounds__(128) void k_prop(float* __restrict__ out) {
    int i = blockIdx.x;
    int t = threadIdx.x;
    float bv = -INFINITY;
    int   bi = 0;
    for (int j = t; j < NSEG; j += 128) {
        if (g_lab[j] != 0) {
            float v = g_aff[i * NSEG + j];
            if (v > bv) { bv = v; bi = j; }   // strict > keeps earliest within stripe
        }
    }
    __shared__ float sv[128];
    __shared__ int   si[128];
    sv[t] = bv; si[t] = bi;
    __syncthreads();
    for (int o = 64; o; o >>= 1) {
        if (t < o) {
            float v2 = sv[t + o]; int i2 = si[t + o];
            if (v2 > sv[t] || (v2 == sv[t] && i2 < si[t])) { sv[t] = v2; si[t] = i2; }
        }
        __syncthreads();
    }
    if (t == 0) {
        int li = g_lab[i];
        int nl = (li == 0 && sv[0] >= 0.7f) ? g_lab[si[0]] : li;
        out[880 + i] = (float)nl;
    }
}

// ---------------- launcher -----------------------------------------------------
extern "C" void kernel_launch(void* const* d_in, const int* in_sizes, int n_in,
                              void* d_out, int out_size) {
    const float* fm = (const float*)d_in[0];
    const int*   sp = (const int*)d_in[1];
    const int*   y  = (const int*)d_in[2];
    const float* W1 = (const float*)d_in[3];
    const float* b1 = (const float*)d_in[4];
    const float* W2 = (const float*)d_in[5];
    const float* b2 = (const float*)d_in[6];
    const float* W3 = (const float*)d_in[7];
    const float* b3 = (const float*)d_in[8];
    const float* Wc = (const float*)d_in[9];
    const float* bc = (const float*)d_in[10];
    float* out = (float*)d_out;

    void *p_feat, *p_h1, *p_h2;
    cudaGetSymbolAddress(&p_feat, g_feat);
    cudaGetSymbolAddress(&p_h1, g_h1);
    cudaGetSymbolAddress(&p_h2, g_h2);

    k_zero<<<(NSEG * NCH + 255) / 256, 256>>>();
    k_hist<<<(HW + 255) / 256, 256>>>(sp, y);
    k_seg<<<dim3(NCH / 8, 4), 256>>>(fm, sp);
    k_lab<<<(NSEG + 255) / 256, 256>>>();
    k_feat<<<NSEG, 256>>>();

    // h1 = relu(feat @ W1 + b1) : (440 x 2112) @ (2112 x 1024)
    k_gemm_relu<<<dim3(NH / 64, (NSEG + 63) / 64), dim3(16, 16)>>>(
        (const float*)p_feat, W1, b1, (float*)p_h1, NSEG, NH, NCH);
    // h2 = relu(h1 @ W2 + b2) : (440 x 1024) @ (1024 x 1024)
    k_gemm_relu<<<dim3(NH / 64, (NSEG + 63) / 64), dim3(16, 16)>>>(
        (const float*)p_h1, W2, b2, (float*)p_h2, NSEG, NH, NH);

    k_head<<<NSEG, 256>>>(W3, b3, Wc, bc, out);
    k_aff<<<dim3((NSEG + 63) / 64, (NSEG + 63) / 64), dim3(16, 16)>>>();
    k_prop<<<NSEG, 128>>>(out);
}

// round 2
// speedup vs baseline: 1.1165x; 1.1165x over previous
#include <cuda_runtime.h>
#include <math.h>

#define NSEG 440
#define NCH  2112
#define HW   65536
#define NH   1024
#define ND   32

// ---------------- scratch (device globals; no allocation allowed) -------------
__device__ float g_sums[NSEG * NCH];
__device__ int   g_cnt[NSEG];
__device__ int   g_hist[NSEG * 3];
__device__ float g_feat[NSEG * NCH];
__device__ float g_fn[NSEG * NCH];
__device__ float g_h1[NSEG * NH];
__device__ float g_h2[NSEG * NH];
__device__ int   g_lab[NSEG];
__device__ float g_aff[NSEG * NSEG];

// ---------------- zero scratch (must run every launch: graph replays) ---------
__global__ void k_zero() {
    int i = blockIdx.x * blockDim.x + threadIdx.x;
    if (i < NSEG * NCH) g_sums[i] = 0.f;
    if (i < NSEG)       g_cnt[i]  = 0;
    if (i < NSEG * 3)   g_hist[i] = 0;
}

// ---------------- per-segment pixel counts + class histogram ------------------
__global__ void k_hist(const int* __restrict__ sp, const int* __restrict__ y) {
    int p = blockIdx.x * blockDim.x + threadIdx.x;
    if (p < HW) {
        int s = sp[p];
        atomicAdd(&g_cnt[s], 1);
        atomicAdd(&g_hist[s * 3 + y[p]], 1);
    }
}

// ---------------- segment feature sums -----------------------------------------
// grid = (NCH/4, 8). Each thread: 1 pixel x 4 channels per iter; coalesced fm
// loads; ONE red.global.add.v4.f32 per (pixel, 4-channel group). 34.6M REDG.128
// total instead of 138M scalar ATOMS.
__global__ __launch_bounds__(256) void k_seg(const float* __restrict__ fm,
                                             const int* __restrict__ sp) {
    int c0   = blockIdx.x * 4;
    int base = blockIdx.y * 8192;
    int t    = threadIdx.x;
    const float* f0 = fm + (size_t)c0 * HW;

#pragma unroll 4
    for (int it = 0; it < 32; ++it) {
        int p = base + it * 256 + t;
        int s = __ldg(&sp[p]);
        float a = __ldg(&f0[p]);
        float b = __ldg(&f0[HW + p]);
        float c = __ldg(&f0[2 * HW + p]);
        float d = __ldg(&f0[3 * HW + p]);
        float* dst = &g_sums[(size_t)s * NCH + c0];
        asm volatile("red.global.add.v4.f32 [%0], {%1,%2,%3,%4};"
                     :: "l"(dst), "f"(a), "f"(b), "f"(c), "f"(d)
                     : "memory");
    }
}

// ---------------- labels from histogram (exact int replication of reference) --
__global__ void k_lab() {
    int s = blockIdx.x * blockDim.x + threadIdx.x;
    if (s < NSEG) {
        int h0 = g_hist[s * 3 + 0];
        int h1 = g_hist[s * 3 + 1];
        int h2 = g_hist[s * 3 + 2];
        int l = 0, best = h0;
        if (h1 > best) { best = h1; l = 1; }   // argmax, first index on ties
        if (h2 > best) { best = h2; l = 2; }
        if (l == 0) l = (h2 > h1) ? 2 : ((h1 > h2) ? 1 : 0);
        g_lab[s] = l;
    }
}

// ---------------- feat = sums/max(cnt,1); fn = feat/||feat|| -------------------
__global__ __launch_bounds__(256) void k_feat() {
    int s = blockIdx.x;
    int t = threadIdx.x;
    float cnt = (float)g_cnt[s];
    if (cnt < 1.f) cnt = 1.f;
    float sq = 0.f;
    for (int c = t; c < NCH; c += 256) {
        float v = g_sums[(size_t)s * NCH + c] / cnt;
        g_feat[(size_t)s * NCH + c] = v;
        sq += v * v;
    }
    __shared__ float red[256];
    red[t] = sq;
    __syncthreads();
    for (int o = 128; o; o >>= 1) {
        if (t < o) red[t] += red[t + o];
        __syncthreads();
    }
    float nrm = sqrtf(red[0]);
    for (int c = t; c < NCH; c += 256) {
        g_fn[(size_t)s * NCH + c] = g_feat[(size_t)s * NCH + c] / nrm;
    }
}

// ---------------- fp32 GEMM: C = relu(A @ B + bias), A:MxK, B:KxN row-major ----
// block 16x16 threads, 64x64 output tile, 4x4 per thread, BK=16.
__global__ __launch_bounds__(256) void k_gemm_relu(
    const float* __restrict__ A, const float* __restrict__ B,
    const float* __restrict__ bias, float* __restrict__ Cout,
    int M, int N, int K)
{
    __shared__ float As[16][64];
    __shared__ float Bs[16][64];
    int tx = threadIdx.x, ty = threadIdx.y;
    int tid = ty * 16 + tx;
    int row0 = blockIdx.y * 64;
    int col0 = blockIdx.x * 64;

    float acc[4][4] = {};

    int aRow = tid >> 2;          // 0..63
    int aCol = (tid & 3) * 4;     // 0,4,8,12
    int bRow = tid >> 4;          // 0..15
    int bCol = (tid & 15) * 4;    // 0..60

    for (int k0 = 0; k0 < K; k0 += 16) {
        float4 av;
        int gm = row0 + aRow;
        if (gm < M) av = *(const float4*)&A[(size_t)gm * K + k0 + aCol];
        else        av = make_float4(0.f, 0.f, 0.f, 0.f);
        As[aCol + 0][aRow] = av.x;
        As[aCol + 1][aRow] = av.y;
        As[aCol + 2][aRow] = av.z;
        As[aCol + 3][aRow] = av.w;

        float4 bv = *(const float4*)&B[(size_t)(k0 + bRow) * N + col0 + bCol];
        *(float4*)&Bs[bRow][bCol] = bv;
        __syncthreads();

#pragma unroll
        for (int kk = 0; kk < 16; ++kk) {
            float4 a = *(float4*)&As[kk][ty * 4];
            float4 b = *(float4*)&Bs[kk][tx * 4];
            float aa[4] = {a.x, a.y, a.z, a.w};
            float bb[4] = {b.x, b.y, b.z, b.w};
#pragma unroll
            for (int i = 0; i < 4; ++i)
#pragma unroll
                for (int j = 0; j < 4; ++j)
                    acc[i][j] += aa[i] * bb[j];
        }
        __syncthreads();
    }

#pragma unroll
    for (int i = 0; i < 4; ++i) {
        int m = row0 + ty * 4 + i;
        if (m < M) {
#pragma unroll
            for (int j = 0; j < 4; ++j) {
                int n = col0 + tx * 4 + j;
                float v = acc[i][j] + bias[n];
                Cout[(size_t)m * N + n] = fmaxf(v, 0.f);
            }
        }
    }
}

// ---------------- affinity: aff[i][j] = expf(-dot(fn_i, fn_j)) -----------------
__global__ __launch_bounds__(256) void k_aff() {
    __shared__ float As[16][64];
    __shared__ float Bs[16][64];
    int tx = threadIdx.x, ty = threadIdx.y;
    int tid = ty * 16 + tx;
    int i0 = blockIdx.y * 64;
    int j0 = blockIdx.x * 64;

    float acc[4][4] = {};

    int aRow = tid >> 2;
    int aCol = (tid & 3) * 4;

    for (int k0 = 0; k0 < NCH; k0 += 16) {
        int gi = i0 + aRow;
        int gj = j0 + aRow;
        float4 av = (gi < NSEG) ? *(const float4*)&g_fn[(size_t)gi * NCH + k0 + aCol]
                                : make_float4(0.f, 0.f, 0.f, 0.f);
        float4 bv = (gj < NSEG) ? *(const float4*)&g_fn[(size_t)gj * NCH + k0 + aCol]
                                : make_float4(0.f, 0.f, 0.f, 0.f);
        As[aCol + 0][aRow] = av.x; As[aCol + 1][aRow] = av.y;
        As[aCol + 2][aRow] = av.z; As[aCol + 3][aRow] = av.w;
        Bs[aCol + 0][aRow] = bv.x; Bs[aCol + 1][aRow] = bv.y;
        Bs[aCol + 2][aRow] = bv.z; Bs[aCol + 3][aRow] = bv.w;
        __syncthreads();

#pragma unroll
        for (int kk = 0; kk < 16; ++kk) {
            float4 a = *(float4*)&As[kk][ty * 4];
            float4 b = *(float4*)&Bs[kk][tx * 4];
            float aa[4] = {a.x, a.y, a.z, a.w};
            float bb[4] = {b.x, b.y, b.z, b.w};
#pragma unroll
            for (int i = 0; i < 4; ++i)
#pragma unroll
                for (int j = 0; j < 4; ++j)
                    acc[i][j] += aa[i] * bb[j];
        }
        __syncthreads();
    }

#pragma unroll
    for (int i = 0; i < 4; ++i) {
        int gi = i0 + ty * 4 + i;
        if (gi < NSEG) {
#pragma unroll
            for (int j = 0; j < 4; ++j) {
                int gj = j0 + tx * 4 + j;
                if (gj < NSEG)
                    g_aff[gi * NSEG + gj] = expf(-acc[i][j]);
            }
        }
    }
}

// ---------------- MLP tail: h3 = relu(h2@W3+b3); pred = softmax(h3@Wc+bc) -----
__global__ __launch_bounds__(256) void k_head(const float* __restrict__ W3,
                                              const float* __restrict__ b3,
                                              const float* __restrict__ Wc,
                                              const float* __restrict__ bc,
                                              float* __restrict__ out) {
    int r = blockIdx.x;
    int t = threadIdx.x;
    int n = t & 31;
    int ks = t >> 5;   // 8 k-slices of 128
    const float* h2r = g_h2 + (size_t)r * NH;

    float acc = 0.f;
    for (int kk = 0; kk < 128; ++kk) {
        int k = ks * 128 + kk;
        acc += h2r[k] * W3[k * 32 + n];
    }
    __shared__ float red[256];
    __shared__ float h3[32];
    red[t] = acc;
    __syncthreads();
    if (t < 32) {
        float v = red[t];
#pragma unroll
        for (int q = 1; q < 8; ++q) v += red[q * 32 + t];
        v += b3[t];
        h3[t] = fmaxf(v, 0.f);
    }
    __syncthreads();
    if (t == 0) {
        float l0 = bc[0], l1 = bc[1];
#pragma unroll
        for (int d = 0; d < 32; ++d) {
            l0 += h3[d] * Wc[d * 2 + 0];
            l1 += h3[d] * Wc[d * 2 + 1];
        }
        float m = fmaxf(l0, l1);
        float e0 = expf(l0 - m), e1 = expf(l1 - m);
        float inv = 1.f / (e0 + e1);
        out[r * 2 + 0] = e0 * inv;
        out[r * 2 + 1] = e1 * inv;
    }
}

// ---------------- label propagation: masked argmax over aff row ---------------
__global__ __launch_bounds__(128) void k_prop(float* __restrict__ out) {
    int i = blockIdx.x;
    int t = threadIdx.x;
    float bv = -INFINITY;
    int   bi = 0;
    for (int j = t; j < NSEG; j += 128) {
        if (g_lab[j] != 0) {
            float v = g_aff[i * NSEG + j];
            if (v > bv) { bv = v; bi = j; }   // strict > keeps earliest within stripe
        }
    }
    __shared__ float sv[128];
    __shared__ int   si[128];
    sv[t] = bv; si[t] = bi;
    __syncthreads();
    for (int o = 64; o; o >>= 1) {
        if (t < o) {
            float v2 = sv[t + o]; int i2 = si[t + o];
            if (v2 > sv[t] || (v2 == sv[t] && i2 < si[t])) { sv[t] = v2; si[t] = i2; }
        }
        __syncthreads();
    }
    if (t == 0) {
        int li = g_lab[i];
        int nl = (li == 0 && sv[0] >= 0.7f) ? g_lab[si[0]] : li;
        out[880 + i] = (float)nl;
    }
}

// ---------------- launcher -----------------------------------------------------
extern "C" void kernel_launch(void* const* d_in, const int* in_sizes, int n_in,
                              void* d_out, int out_size) {
    const float* fm = (const float*)d_in[0];
    const int*   sp = (const int*)d_in[1];
    const int*   y  = (const int*)d_in[2];
    const float* W1 = (const float*)d_in[3];
    const float* b1 = (const float*)d_in[4];
    const float* W2 = (const float*)d_in[5];
    const float* b2 = (const float*)d_in[6];
    const float* W3 = (const float*)d_in[7];
    const float* b3 = (const float*)d_in[8];
    const float* Wc = (const float*)d_in[9];
    const float* bc = (const float*)d_in[10];
    float* out = (float*)d_out;

    void *p_feat, *p_h1, *p_h2;
    cudaGetSymbolAddress(&p_feat, g_feat);
    cudaGetSymbolAddress(&p_h1, g_h1);
    cudaGetSymbolAddress(&p_h2, g_h2);

    k_zero<<<(NSEG * NCH + 255) / 256, 256>>>();
    k_hist<<<(HW + 255) / 256, 256>>>(sp, y);
    k_seg<<<dim3(NCH / 4, 8), 256>>>(fm, sp);
    k_lab<<<(NSEG + 255) / 256, 256>>>();
    k_feat<<<NSEG, 256>>>();

    // h1 = relu(feat @ W1 + b1) : (440 x 2112) @ (2112 x 1024)
    k_gemm_relu<<<dim3(NH / 64, (NSEG + 63) / 64), dim3(16, 16)>>>(
        (const float*)p_feat, W1, b1, (float*)p_h1, NSEG, NH, NCH);
    // h2 = relu(h1 @ W2 + b2) : (440 x 1024) @ (1024 x 1024)
    k_gemm_relu<<<dim3(NH / 64, (NSEG + 63) / 64), dim3(16, 16)>>>(
        (const float*)p_h1, W2, b2, (float*)p_h2, NSEG, NH, NH);

    k_head<<<NSEG, 256>>>(W3, b3, Wc, bc, out);
    k_aff<<<dim3((NSEG + 63) / 64, (NSEG + 63) / 64), dim3(16, 16)>>>();
    k_prop<<<NSEG, 128>>>(out);
}